// round 1
// baseline (speedup 1.0000x reference)
#include <cuda_runtime.h>
#include <math.h>

#define Nn 50000
#define Ee 1600000
#define Hh 128
#define NUc 49232
#define NMc 512
#define NSc 256

// ---------------- scratch (static device globals; no allocation) ----------------
__device__ float g_hm[(size_t)Nn * Hh];   // GEMM output (pre-aggregation), reused per layer
__device__ float g_ha[(size_t)Nn * Hh];   // ping
__device__ float g_hb[(size_t)Nn * Hh];   // pong
__device__ float g_el[Nn];
__device__ float g_er[Nn];
__device__ int   g_cnt[Nn];
__device__ int   g_rowptr[Nn + 1];
__device__ int   g_cursor[Nn];
__device__ int   g_ssrc[Ee];
__device__ float g_T[NMc * Hh];

// ---------------- CSR build ----------------
__global__ void zero_cnt_kernel() {
    int i = blockIdx.x * blockDim.x + threadIdx.x;
    if (i < Nn) g_cnt[i] = 0;
}

__global__ void hist_kernel(const int* __restrict__ dst) {
    for (int i = blockIdx.x * blockDim.x + threadIdx.x; i < Ee; i += gridDim.x * blockDim.x)
        atomicAdd(&g_cnt[dst[i]], 1);
}

__global__ void scan_kernel() {
    const int T = 1024;
    const int chunk = (Nn + T - 1) / T;
    int t = threadIdx.x;
    int s0 = t * chunk;
    int s1 = min(s0 + chunk, Nn);
    int sum = 0;
    for (int i = s0; i < s1; ++i) sum += g_cnt[i];
    __shared__ int ps[1024];
    ps[t] = sum;
    __syncthreads();
    for (int off = 1; off < 1024; off <<= 1) {
        int v = (t >= off) ? ps[t - off] : 0;
        __syncthreads();
        ps[t] += v;
        __syncthreads();
    }
    int incl = ps[t];
    int run = incl - sum;  // exclusive prefix for this chunk
    for (int i = s0; i < s1; ++i) {
        g_rowptr[i] = run;
        g_cursor[i] = run;
        run += g_cnt[i];
    }
    if (s0 < Nn && s1 == Nn) g_rowptr[Nn] = run;
}

__global__ void scatter_kernel(const int* __restrict__ src, const int* __restrict__ dst) {
    for (int i = blockIdx.x * blockDim.x + threadIdx.x; i < Ee; i += gridDim.x * blockDim.x) {
        int d = dst[i];
        int p = atomicAdd(&g_cursor[d], 1);
        g_ssrc[p] = src[i];
    }
}

// ---------------- GEMM: Hout[r][:] = X[r][:] @ W(128x128), optional el/er epilogue ----------------
__global__ void gemm_el_kernel(const float* __restrict__ X, const float* __restrict__ W,
                               const float* __restrict__ al, const float* __restrict__ ar,
                               float* __restrict__ Hout, int nrows, int compute_elr) {
    extern __shared__ float Ws[];  // 128*128 floats = 64KB
    for (int i = threadIdx.x; i < (Hh * Hh) / 4; i += blockDim.x)
        ((float4*)Ws)[i] = ((const float4*)W)[i];
    __syncthreads();

    const unsigned FULL = 0xffffffffu;
    int lane = threadIdx.x & 31;
    int warp = threadIdx.x >> 5;
    int warps_per_block = blockDim.x >> 5;
    int gw = blockIdx.x * warps_per_block + warp;
    int nwarps = gridDim.x * warps_per_block;

    float4 al4 = make_float4(0.f, 0.f, 0.f, 0.f);
    float4 ar4 = make_float4(0.f, 0.f, 0.f, 0.f);
    if (compute_elr) {
        al4 = ((const float4*)al)[lane];
        ar4 = ((const float4*)ar)[lane];
    }

    int ngroups = (nrows + 3) >> 2;
    for (int g = gw; g < ngroups; g += nwarps) {
        int row0 = g * 4;
        float4 xr[4];
#pragma unroll
        for (int r = 0; r < 4; ++r) {
            int row = row0 + r;
            xr[r] = (row < nrows) ? ((const float4*)(X + (size_t)row * Hh))[lane]
                                  : make_float4(0.f, 0.f, 0.f, 0.f);
        }
        float4 acc[4];
#pragma unroll
        for (int r = 0; r < 4; ++r) acc[r] = make_float4(0.f, 0.f, 0.f, 0.f);

#pragma unroll 8
        for (int kk = 0; kk < 32; ++kk) {
            float xv[4][4];
#pragma unroll
            for (int r = 0; r < 4; ++r) {
                xv[r][0] = __shfl_sync(FULL, xr[r].x, kk);
                xv[r][1] = __shfl_sync(FULL, xr[r].y, kk);
                xv[r][2] = __shfl_sync(FULL, xr[r].z, kk);
                xv[r][3] = __shfl_sync(FULL, xr[r].w, kk);
            }
#pragma unroll
            for (int q = 0; q < 4; ++q) {
                float4 wv = ((const float4*)Ws)[(kk * 4 + q) * 32 + lane];
#pragma unroll
                for (int r = 0; r < 4; ++r) {
                    acc[r].x += xv[r][q] * wv.x;
                    acc[r].y += xv[r][q] * wv.y;
                    acc[r].z += xv[r][q] * wv.z;
                    acc[r].w += xv[r][q] * wv.w;
                }
            }
        }

#pragma unroll
        for (int r = 0; r < 4; ++r) {
            int row = row0 + r;
            if (row >= nrows) continue;
            ((float4*)(Hout + (size_t)row * Hh))[lane] = acc[r];
            if (compute_elr) {
                float dl = acc[r].x * al4.x + acc[r].y * al4.y + acc[r].z * al4.z + acc[r].w * al4.w;
                float dr = acc[r].x * ar4.x + acc[r].y * ar4.y + acc[r].z * ar4.z + acc[r].w * ar4.w;
#pragma unroll
                for (int o = 16; o; o >>= 1) {
                    dl += __shfl_xor_sync(FULL, dl, o);
                    dr += __shfl_xor_sync(FULL, dr, o);
                }
                if (lane == 0) {
                    g_el[row] = dl;
                    g_er[row] = dr;
                }
            }
        }
    }
}

// ---------------- fused edge softmax + aggregation (warp per dst node) ----------------
__global__ void agg_kernel(const float* __restrict__ h, const float* __restrict__ bias,
                           float* __restrict__ hout, int do_relu) {
    const unsigned FULL = 0xffffffffu;
    int lane = threadIdx.x & 31;
    int v = (blockIdx.x * blockDim.x + threadIdx.x) >> 5;
    if (v >= Nn) return;

    int r0 = g_rowptr[v];
    int r1 = g_rowptr[v + 1];
    float elv = g_el[v];

    // pass 1: segment max (lanes strided over edges)
    float m = -3.402823466e38f;
    for (int i = r0 + lane; i < r1; i += 32) {
        float e = elv + g_er[g_ssrc[i]];
        e = e > 0.f ? e : 0.2f * e;
        m = fmaxf(m, e);
    }
#pragma unroll
    for (int o = 16; o; o >>= 1) m = fmaxf(m, __shfl_xor_sync(FULL, m, o));

    // pass 2: weighted vector accumulate (full warp per edge; lane owns 4 dims)
    float4 acc = make_float4(0.f, 0.f, 0.f, 0.f);
    float s = 0.f;
#pragma unroll 2
    for (int i = r0; i < r1; ++i) {
        int sv = g_ssrc[i];
        float e = elv + g_er[sv];
        e = e > 0.f ? e : 0.2f * e;
        float w = __expf(e - m);
        s += w;
        float4 hv = *(const float4*)(h + (size_t)sv * Hh + lane * 4);
        acc.x += w * hv.x;
        acc.y += w * hv.y;
        acc.z += w * hv.z;
        acc.w += w * hv.w;
    }

    float inv = 1.f / (s + 1e-10f);
    float4 bv = *(const float4*)(bias + lane * 4);
    float4 o;
    o.x = acc.x * inv + bv.x;
    o.y = acc.y * inv + bv.y;
    o.z = acc.z * inv + bv.z;
    o.w = acc.w * inv + bv.w;
    if (do_relu) {
        o.x = fmaxf(o.x, 0.f);
        o.y = fmaxf(o.y, 0.f);
        o.z = fmaxf(o.z, 0.f);
        o.w = fmaxf(o.w, 0.f);
    }
    *(float4*)(hout + (size_t)v * Hh + lane * 4) = o;
}

// ---------------- scores = T @ server^T + bb (warp per model row) ----------------
__global__ void scores_kernel(const float* __restrict__ Tm, const float* __restrict__ S,
                              const float* __restrict__ bb, float* __restrict__ out) {
    const unsigned FULL = 0xffffffffu;
    int lane = threadIdx.x & 31;
    int m = (blockIdx.x * blockDim.x + threadIdx.x) >> 5;
    if (m >= NMc) return;
    float4 t = ((const float4*)(Tm + (size_t)m * Hh))[lane];
    float b = bb[0];
    for (int sidx = 0; sidx < NSc; ++sidx) {
        float4 sv = ((const float4*)(S + (size_t)sidx * Hh))[lane];
        float d = t.x * sv.x + t.y * sv.y + t.z * sv.z + t.w * sv.w;
#pragma unroll
        for (int o = 16; o; o >>= 1) d += __shfl_xor_sync(FULL, d, o);
        if (lane == 0) out[m * NSc + sidx] = d + b;
    }
}

// ---------------- launch ----------------
extern "C" void kernel_launch(void* const* d_in, const int* in_sizes, int n_in,
                              void* d_out, int out_size) {
    (void)in_sizes; (void)n_in; (void)out_size;
    const float* x   = (const float*)d_in[0];
    const int*   ei  = (const int*)d_in[1];
    const float* W1  = (const float*)d_in[2];
    const float* al1 = (const float*)d_in[3];
    const float* ar1 = (const float*)d_in[4];
    const float* b1  = (const float*)d_in[5];
    const float* W2  = (const float*)d_in[6];
    const float* al2 = (const float*)d_in[7];
    const float* ar2 = (const float*)d_in[8];
    const float* b2  = (const float*)d_in[9];
    const float* W3  = (const float*)d_in[10];
    const float* al3 = (const float*)d_in[11];
    const float* ar3 = (const float*)d_in[12];
    const float* b3  = (const float*)d_in[13];
    const float* Wb  = (const float*)d_in[14];
    const float* bb  = (const float*)d_in[15];
    float* out = (float*)d_out;

    const int* src = ei;
    const int* dst = ei + Ee;

    cudaFuncSetAttribute(gemm_el_kernel, cudaFuncAttributeMaxDynamicSharedMemorySize, 65536);

    float *hm, *ha, *hb, *Tp;
    cudaGetSymbolAddress((void**)&hm, g_hm);
    cudaGetSymbolAddress((void**)&ha, g_ha);
    cudaGetSymbolAddress((void**)&hb, g_hb);
    cudaGetSymbolAddress((void**)&Tp, g_T);

    // CSR by dst
    zero_cnt_kernel<<<(Nn + 255) / 256, 256>>>();
    hist_kernel<<<4096, 256>>>(dst);
    scan_kernel<<<1, 1024>>>();
    scatter_kernel<<<4096, 256>>>(src, dst);

    const int GEMM_GRID = 448;
    const int AGG_GRID  = (Nn * 32 + 255) / 256;

    // layer 1
    gemm_el_kernel<<<GEMM_GRID, 256, 65536>>>(x, W1, al1, ar1, hm, Nn, 1);
    agg_kernel<<<AGG_GRID, 256>>>(hm, b1, ha, 1);
    // layer 2
    gemm_el_kernel<<<GEMM_GRID, 256, 65536>>>(ha, W2, al2, ar2, hm, Nn, 1);
    agg_kernel<<<AGG_GRID, 256>>>(hm, b2, hb, 1);
    // layer 3
    gemm_el_kernel<<<GEMM_GRID, 256, 65536>>>(hb, W3, al3, ar3, hm, Nn, 1);
    agg_kernel<<<AGG_GRID, 256>>>(hm, b3, ha, 0);

    // bilinear head: T = model_emb @ Wb, then scores = T @ server^T + bb
    gemm_el_kernel<<<32, 256, 65536>>>(ha + (size_t)NUc * Hh, Wb, al1, ar1, Tp, NMc, 0);
    scores_kernel<<<64, 256>>>(Tp, ha + (size_t)(NUc + NMc) * Hh, bb, out);
}

// round 3
// speedup vs baseline: 1.2932x; 1.2932x over previous
#include <cuda_runtime.h>
#include <cuda_bf16.h>
#include <math.h>
#include <stdint.h>

#define Nn 50000
#define Ee 1600000
#define Hh 128
#define NUc 49232
#define NMc 512
#define NSc 256
#define NB 196   // ceil(Nn/256)

// ---------------- scratch (static device globals; no allocation) ----------------
__device__ float g_hm[(size_t)Nn * Hh];   // GEMM output (pre-aggregation), reused per layer
__device__ float g_ha[(size_t)Nn * Hh];   // ping
__device__ float g_hb[(size_t)Nn * Hh];   // pong
__device__ float g_el[Nn];
__device__ float g_er[Nn];
__device__ int   g_cnt[Nn];
__device__ int   g_rowptr[Nn + 1];
__device__ int   g_cursor[Nn];
__device__ int   g_ssrc[Ee];
__device__ float g_T[NMc * Hh];
__device__ int   g_bsum[NB];
__device__ int   g_boff[NB];

// ---------------- CSR build ----------------
__global__ void zero_cnt_kernel() {
    int i = blockIdx.x * blockDim.x + threadIdx.x;
    if (i < Nn) g_cnt[i] = 0;
}

__global__ void hist_kernel(const int* __restrict__ dst) {
    int stride = gridDim.x * blockDim.x;
#pragma unroll 4
    for (int i = blockIdx.x * blockDim.x + threadIdx.x; i < Ee; i += stride)
        atomicAdd(&g_cnt[dst[i]], 1);
}

// block-level reduction of g_cnt -> g_bsum
__global__ void scanA_kernel() {
    __shared__ int ws[8];
    int t = threadIdx.x, lane = t & 31, warp = t >> 5;
    int i = blockIdx.x * 256 + t;
    int v = (i < Nn) ? g_cnt[i] : 0;
    int x = v;
#pragma unroll
    for (int o = 16; o; o >>= 1) x += __shfl_xor_sync(0xffffffffu, x, o);
    if (lane == 0) ws[warp] = x;
    __syncthreads();
    if (t == 0) {
        int s = 0;
#pragma unroll
        for (int w = 0; w < 8; ++w) s += ws[w];
        g_bsum[blockIdx.x] = s;
    }
}

// exclusive scan of NB block sums -> g_boff (single block Hillis-Steele)
__global__ void scanB_kernel() {
    __shared__ int s[256];
    int t = threadIdx.x;
    s[t] = (t < NB) ? g_bsum[t] : 0;
    __syncthreads();
#pragma unroll
    for (int off = 1; off < 256; off <<= 1) {
        int v = (t >= off) ? s[t - off] : 0;
        __syncthreads();
        s[t] += v;
        __syncthreads();
    }
    if (t < NB) g_boff[t] = s[t] - g_bsum[t];   // exclusive
    if (t == 0) g_rowptr[Nn] = Ee;
}

// per-block inclusive scan + offset -> rowptr / cursor
__global__ void scanC_kernel() {
    __shared__ int s[256];
    int t = threadIdx.x;
    int i = blockIdx.x * 256 + t;
    int v = (i < Nn) ? g_cnt[i] : 0;
    s[t] = v;
    __syncthreads();
#pragma unroll
    for (int off = 1; off < 256; off <<= 1) {
        int q = (t >= off) ? s[t - off] : 0;
        __syncthreads();
        s[t] += q;
        __syncthreads();
    }
    if (i < Nn) {
        int excl = s[t] - v + g_boff[blockIdx.x];
        g_rowptr[i] = excl;
        g_cursor[i] = excl;
    }
}

__global__ void scatter_kernel(const int* __restrict__ src, const int* __restrict__ dst) {
    int stride = gridDim.x * blockDim.x;
#pragma unroll 4
    for (int i = blockIdx.x * blockDim.x + threadIdx.x; i < Ee; i += stride) {
        int d = dst[i];
        int p = atomicAdd(&g_cursor[d], 1);
        g_ssrc[p] = src[i];
    }
}

// ---------------- tf32 tensor-core GEMM, error-compensated (hi in tf32, lo in bf16) ----------
__device__ __forceinline__ uint32_t f2tf32(float x) {
    uint32_t r;
    asm("cvt.rna.tf32.f32 %0, %1;" : "=r"(r) : "f"(x));
    return r;
}
__device__ __forceinline__ void mma_tf32(float c[4], const uint32_t a[4], uint32_t b0, uint32_t b1) {
    asm volatile(
        "mma.sync.aligned.m16n8k8.row.col.f32.tf32.tf32.f32 "
        "{%0,%1,%2,%3}, {%4,%5,%6,%7}, {%8,%9}, {%0,%1,%2,%3};"
        : "+f"(c[0]), "+f"(c[1]), "+f"(c[2]), "+f"(c[3])
        : "r"(a[0]), "r"(a[1]), "r"(a[2]), "r"(a[3]), "r"(b0), "r"(b1));
}

#define WPAD 136   // bank = (8*tig + g) mod 32 -> conflict-free
#define WPADH 272  // bf16 row pad (bytes pattern matches: 272*2 = 544 bytes/row; bank of elem = ((tig*272+n0+g)*2/4)%32 -> (tig*136+..)%32 = same as float WPAD)

__global__ void gemm_tf32_kernel(const float* __restrict__ X, const float* __restrict__ W,
                                 const float* __restrict__ al, const float* __restrict__ ar,
                                 float* __restrict__ Hout, int nrows, int compute_elr) {
    extern __shared__ float smem[];                     // Whi[128][136] fp32 | Wlo[128][272] bf16
    float* Whi = smem;
    __nv_bfloat16* Wlo = (__nv_bfloat16*)(smem + 128 * WPAD);

    for (int i = threadIdx.x; i < Hh * Hh; i += blockDim.x) {
        int k = i >> 7, n = i & 127;
        float w = W[i];
        uint32_t hb = f2tf32(w);
        float hf = __uint_as_float(hb);
        Whi[k * WPAD + n] = hf;
        Wlo[k * WPADH + n] = __float2bfloat16(w - hf);
    }
    __syncthreads();

    const unsigned FULL = 0xffffffffu;
    int lane = threadIdx.x & 31;
    int warp = threadIdx.x >> 5;
    int g = lane >> 2, tig = lane & 3;
    int gw = blockIdx.x * (blockDim.x >> 5) + warp;
    int nwarps = gridDim.x * (blockDim.x >> 5);
    int ngroups = (nrows + 15) >> 4;

    for (int grp = gw; grp < ngroups; grp += nwarps) {
        int row0 = grp * 16;
        int rA = row0 + g, rB = row0 + g + 8;
        bool vA = rA < nrows, vB = rB < nrows;

        float c[16][4];
#pragma unroll
        for (int nt = 0; nt < 16; ++nt) {
            c[nt][0] = 0.f; c[nt][1] = 0.f; c[nt][2] = 0.f; c[nt][3] = 0.f;
        }

#pragma unroll 2
        for (int kt = 0; kt < 16; ++kt) {
            int k0 = kt * 8;
            float af[4];
            af[0] = vA ? X[(size_t)rA * Hh + k0 + tig]     : 0.f;
            af[1] = vB ? X[(size_t)rB * Hh + k0 + tig]     : 0.f;
            af[2] = vA ? X[(size_t)rA * Hh + k0 + tig + 4] : 0.f;
            af[3] = vB ? X[(size_t)rB * Hh + k0 + tig + 4] : 0.f;
            uint32_t ahi[4], alo[4];
#pragma unroll
            for (int q = 0; q < 4; ++q) {
                ahi[q] = f2tf32(af[q]);
                alo[q] = f2tf32(af[q] - __uint_as_float(ahi[q]));
            }
#pragma unroll
            for (int nt = 0; nt < 16; ++nt) {
                int n0 = nt * 8;
                uint32_t bh0 = __float_as_uint(Whi[(k0 + tig) * WPAD + n0 + g]);
                uint32_t bh1 = __float_as_uint(Whi[(k0 + tig + 4) * WPAD + n0 + g]);
                uint32_t bl0 = f2tf32(__bfloat162float(Wlo[(k0 + tig) * WPADH + n0 + g]));
                uint32_t bl1 = f2tf32(__bfloat162float(Wlo[(k0 + tig + 4) * WPADH + n0 + g]));
                mma_tf32(c[nt], ahi, bh0, bh1);   // hi*hi
                mma_tf32(c[nt], ahi, bl0, bl1);   // hi*lo
                mma_tf32(c[nt], alo, bh0, bh1);   // lo*hi
            }
        }

        // epilogue: store H rows + fused el/er dot products
        float pal = 0.f, par = 0.f, pbl = 0.f, pbr = 0.f;
#pragma unroll
        for (int nt = 0; nt < 16; ++nt) {
            int col = nt * 8 + 2 * tig;
            if (vA) *(float2*)&Hout[(size_t)rA * Hh + col] = make_float2(c[nt][0], c[nt][1]);
            if (vB) *(float2*)&Hout[(size_t)rB * Hh + col] = make_float2(c[nt][2], c[nt][3]);
            if (compute_elr) {
                float a0 = al[col], a1 = al[col + 1];
                float r0v = ar[col], r1v = ar[col + 1];
                pal += c[nt][0] * a0 + c[nt][1] * a1;
                par += c[nt][0] * r0v + c[nt][1] * r1v;
                pbl += c[nt][2] * a0 + c[nt][3] * a1;
                pbr += c[nt][2] * r0v + c[nt][3] * r1v;
            }
        }
        if (compute_elr) {
#pragma unroll
            for (int o = 1; o < 4; o <<= 1) {
                pal += __shfl_xor_sync(FULL, pal, o);
                par += __shfl_xor_sync(FULL, par, o);
                pbl += __shfl_xor_sync(FULL, pbl, o);
                pbr += __shfl_xor_sync(FULL, pbr, o);
            }
            if (tig == 0) {
                if (vA) { g_el[rA] = pal; g_er[rA] = par; }
                if (vB) { g_el[rB] = pbl; g_er[rB] = pbr; }
            }
        }
    }
}

// ---------------- fused edge softmax + aggregation (single pass, no max) ----------------
__global__ void agg_kernel(const float* __restrict__ h, const float* __restrict__ bias,
                           float* __restrict__ hout, int do_relu) {
    int lane = threadIdx.x & 31;
    int v = (blockIdx.x * blockDim.x + threadIdx.x) >> 5;
    if (v >= Nn) return;

    int r0 = g_rowptr[v];
    int r1 = g_rowptr[v + 1];
    float elv = g_el[v];

    float4 acc = make_float4(0.f, 0.f, 0.f, 0.f);
    float s = 0.f;
#pragma unroll 4
    for (int i = r0; i < r1; ++i) {
        int sv = g_ssrc[i];
        float e = elv + g_er[sv];
        e = e > 0.f ? e : 0.2f * e;
        float w = __expf(e);
        s += w;
        float4 hv = *(const float4*)(h + (size_t)sv * Hh + lane * 4);
        acc.x += w * hv.x;
        acc.y += w * hv.y;
        acc.z += w * hv.z;
        acc.w += w * hv.w;
    }

    float inv = 1.f / (s + 1e-10f);
    float4 bv = *(const float4*)(bias + lane * 4);
    float4 o;
    o.x = acc.x * inv + bv.x;
    o.y = acc.y * inv + bv.y;
    o.z = acc.z * inv + bv.z;
    o.w = acc.w * inv + bv.w;
    if (do_relu) {
        o.x = fmaxf(o.x, 0.f);
        o.y = fmaxf(o.y, 0.f);
        o.z = fmaxf(o.z, 0.f);
        o.w = fmaxf(o.w, 0.f);
    }
    *(float4*)(hout + (size_t)v * Hh + lane * 4) = o;
}

// ---------------- scores = T @ server^T + bb (warp per (model row, 32-server chunk)) ----------------
__global__ void scores_kernel(const float* __restrict__ Tm, const float* __restrict__ S,
                              const float* __restrict__ bb, float* __restrict__ out) {
    const unsigned FULL = 0xffffffffu;
    int lane = threadIdx.x & 31;
    int w = (blockIdx.x * blockDim.x + threadIdx.x) >> 5;
    if (w >= NMc * 8) return;
    int m = w >> 3;
    int sbase = (w & 7) * 32;
    float4 t = ((const float4*)(Tm + (size_t)m * Hh))[lane];
    float b = bb[0];
    for (int j = 0; j < 32; ++j) {
        int sidx = sbase + j;
        float4 sv = ((const float4*)(S + (size_t)sidx * Hh))[lane];
        float d = t.x * sv.x + t.y * sv.y + t.z * sv.z + t.w * sv.w;
#pragma unroll
        for (int o = 16; o; o >>= 1) d += __shfl_xor_sync(FULL, d, o);
        if (lane == 0) out[m * NSc + sidx] = d + b;
    }
}

// ---------------- launch ----------------
extern "C" void kernel_launch(void* const* d_in, const int* in_sizes, int n_in,
                              void* d_out, int out_size) {
    (void)in_sizes; (void)n_in; (void)out_size;
    const float* x   = (const float*)d_in[0];
    const int*   ei  = (const int*)d_in[1];
    const float* W1  = (const float*)d_in[2];
    const float* al1 = (const float*)d_in[3];
    const float* ar1 = (const float*)d_in[4];
    const float* b1  = (const float*)d_in[5];
    const float* W2  = (const float*)d_in[6];
    const float* al2 = (const float*)d_in[7];
    const float* ar2 = (const float*)d_in[8];
    const float* b2  = (const float*)d_in[9];
    const float* W3  = (const float*)d_in[10];
    const float* al3 = (const float*)d_in[11];
    const float* ar3 = (const float*)d_in[12];
    const float* b3  = (const float*)d_in[13];
    const float* Wb  = (const float*)d_in[14];
    const float* bb  = (const float*)d_in[15];
    float* out = (float*)d_out;

    const int* src = ei;
    const int* dst = ei + Ee;

    const int SMEM_GEMM = 128 * WPAD * 4 + 128 * WPADH * 2;   // 69632 + 69632 = ... (see note)
    cudaFuncSetAttribute(gemm_tf32_kernel, cudaFuncAttributeMaxDynamicSharedMemorySize, SMEM_GEMM);

    float *hm, *ha, *hb, *Tp;
    cudaGetSymbolAddress((void**)&hm, g_hm);
    cudaGetSymbolAddress((void**)&ha, g_ha);
    cudaGetSymbolAddress((void**)&hb, g_hb);
    cudaGetSymbolAddress((void**)&Tp, g_T);

    // CSR by dst
    zero_cnt_kernel<<<NB, 256>>>();
    hist_kernel<<<2048, 256>>>(dst);
    scanA_kernel<<<NB, 256>>>();
    scanB_kernel<<<1, 256>>>();
    scanC_kernel<<<NB, 256>>>();
    scatter_kernel<<<2048, 256>>>(src, dst);

    const int GEMM_GRID = 391;                  // ceil(50000/128) row groups of 16 x 8 warps
    const int AGG_GRID  = (Nn * 32 + 255) / 256;

    // layer 1
    gemm_tf32_kernel<<<GEMM_GRID, 256, SMEM_GEMM>>>(x, W1, al1, ar1, hm, Nn, 1);
    agg_kernel<<<AGG_GRID, 256>>>(hm, b1, ha, 1);
    // layer 2
    gemm_tf32_kernel<<<GEMM_GRID, 256, SMEM_GEMM>>>(ha, W2, al2, ar2, hm, Nn, 1);
    agg_kernel<<<AGG_GRID, 256>>>(hm, b2, hb, 1);
    // layer 3
    gemm_tf32_kernel<<<GEMM_GRID, 256, SMEM_GEMM>>>(hb, W3, al3, ar3, hm, Nn, 1);
    agg_kernel<<<AGG_GRID, 256>>>(hm, b3, ha, 0);

    // bilinear head: T = model_emb @ Wb, then scores = T @ server^T + bb
    gemm_tf32_kernel<<<4, 256, SMEM_GEMM>>>(ha + (size_t)NUc * Hh, Wb, al1, ar1, Tp, NMc, 0);
    scores_kernel<<<512, 256>>>(Tp, ha + (size_t)(NUc + NMc) * Hh, bb, out);
}

// round 4
// speedup vs baseline: 1.2965x; 1.0026x over previous
#include <cuda_runtime.h>
#include <cuda_fp16.h>
#include <cuda_bf16.h>
#include <math.h>
#include <stdint.h>

#define Nn 50000
#define Ee 1600000
#define Hh 128
#define NUc 49232
#define NMc 512
#define NSc 256
#define NB 196   // ceil(Nn/256)

// ---------------- scratch (static device globals; no allocation) ----------------
__device__ __half g_hm[(size_t)Nn * Hh];  // GEMM output (pre-aggregation), fp16, reused per layer
__device__ float  g_ha[(size_t)Nn * Hh];  // ping (agg output, fp32)
__device__ float  g_hb[(size_t)Nn * Hh];  // pong
__device__ float  g_el[Nn];
__device__ float  g_er[Nn];
__device__ int    g_cnt[Nn];
__device__ int    g_rowptr[Nn + 1];
__device__ int    g_cursor[Nn];
__device__ int    g_ssrc[Ee];
__device__ __half g_T[NMc * Hh];
__device__ int    g_bsum[NB];
__device__ int    g_boff[NB];

// ---------------- CSR build ----------------
__global__ void zero_cnt_kernel() {
    int i = blockIdx.x * blockDim.x + threadIdx.x;
    if (i < Nn) g_cnt[i] = 0;
}

__global__ void hist_kernel(const int* __restrict__ dst) {
    int stride = gridDim.x * blockDim.x;
#pragma unroll 4
    for (int i = blockIdx.x * blockDim.x + threadIdx.x; i < Ee; i += stride)
        atomicAdd(&g_cnt[dst[i]], 1);
}

// block-level reduction of g_cnt -> g_bsum
__global__ void scanA_kernel() {
    __shared__ int ws[8];
    int t = threadIdx.x, lane = t & 31, warp = t >> 5;
    int i = blockIdx.x * 256 + t;
    int v = (i < Nn) ? g_cnt[i] : 0;
    int x = v;
#pragma unroll
    for (int o = 16; o; o >>= 1) x += __shfl_xor_sync(0xffffffffu, x, o);
    if (lane == 0) ws[warp] = x;
    __syncthreads();
    if (t == 0) {
        int s = 0;
#pragma unroll
        for (int w = 0; w < 8; ++w) s += ws[w];
        g_bsum[blockIdx.x] = s;
    }
}

// exclusive scan of NB block sums -> g_boff (single block)
__global__ void scanB_kernel() {
    __shared__ int s[256];
    int t = threadIdx.x;
    s[t] = (t < NB) ? g_bsum[t] : 0;
    __syncthreads();
#pragma unroll
    for (int off = 1; off < 256; off <<= 1) {
        int v = (t >= off) ? s[t - off] : 0;
        __syncthreads();
        s[t] += v;
        __syncthreads();
    }
    if (t < NB) g_boff[t] = s[t] - g_bsum[t];   // exclusive
    if (t == 0) g_rowptr[Nn] = Ee;
}

// per-block inclusive scan + offset -> rowptr / cursor
__global__ void scanC_kernel() {
    __shared__ int s[256];
    int t = threadIdx.x;
    int i = blockIdx.x * 256 + t;
    int v = (i < Nn) ? g_cnt[i] : 0;
    s[t] = v;
    __syncthreads();
#pragma unroll
    for (int off = 1; off < 256; off <<= 1) {
        int q = (t >= off) ? s[t - off] : 0;
        __syncthreads();
        s[t] += q;
        __syncthreads();
    }
    if (i < Nn) {
        int excl = s[t] - v + g_boff[blockIdx.x];
        g_rowptr[i] = excl;
        g_cursor[i] = excl;
    }
}

__global__ void scatter_kernel(const int* __restrict__ src, const int* __restrict__ dst) {
    int stride = gridDim.x * blockDim.x;
#pragma unroll 4
    for (int i = blockIdx.x * blockDim.x + threadIdx.x; i < Ee; i += stride) {
        int d = dst[i];
        int p = atomicAdd(&g_cursor[d], 1);
        g_ssrc[p] = src[i];
    }
}

// ---------------- tf32 tensor-core GEMM, error-compensated (hi in tf32, lo in bf16) ----------
// Output h written in fp16; el/er from fp32 accumulators.
__device__ __forceinline__ uint32_t f2tf32(float x) {
    uint32_t r;
    asm("cvt.rna.tf32.f32 %0, %1;" : "=r"(r) : "f"(x));
    return r;
}
__device__ __forceinline__ void mma_tf32(float c[4], const uint32_t a[4], uint32_t b0, uint32_t b1) {
    asm volatile(
        "mma.sync.aligned.m16n8k8.row.col.f32.tf32.tf32.f32 "
        "{%0,%1,%2,%3}, {%4,%5,%6,%7}, {%8,%9}, {%0,%1,%2,%3};"
        : "+f"(c[0]), "+f"(c[1]), "+f"(c[2]), "+f"(c[3])
        : "r"(a[0]), "r"(a[1]), "r"(a[2]), "r"(a[3]), "r"(b0), "r"(b1));
}

#define WPAD 136
#define WPADH 272

__global__ void gemm_tf32_kernel(const float* __restrict__ X, const float* __restrict__ W,
                                 const float* __restrict__ al, const float* __restrict__ ar,
                                 __half* __restrict__ Hout, int nrows, int compute_elr) {
    extern __shared__ float smem[];                     // Whi[128][136] fp32 | Wlo[128][272] bf16
    float* Whi = smem;
    __nv_bfloat16* Wlo = (__nv_bfloat16*)(smem + 128 * WPAD);

    for (int i = threadIdx.x; i < Hh * Hh; i += blockDim.x) {
        int k = i >> 7, n = i & 127;
        float w = W[i];
        uint32_t hb = f2tf32(w);
        float hf = __uint_as_float(hb);
        Whi[k * WPAD + n] = hf;
        Wlo[k * WPADH + n] = __float2bfloat16(w - hf);
    }
    __syncthreads();

    const unsigned FULL = 0xffffffffu;
    int lane = threadIdx.x & 31;
    int warp = threadIdx.x >> 5;
    int g = lane >> 2, tig = lane & 3;
    int gw = blockIdx.x * (blockDim.x >> 5) + warp;
    int nwarps = gridDim.x * (blockDim.x >> 5);
    int ngroups = (nrows + 15) >> 4;

    for (int grp = gw; grp < ngroups; grp += nwarps) {
        int row0 = grp * 16;
        int rA = row0 + g, rB = row0 + g + 8;
        bool vA = rA < nrows, vB = rB < nrows;

        float c[16][4];
#pragma unroll
        for (int nt = 0; nt < 16; ++nt) {
            c[nt][0] = 0.f; c[nt][1] = 0.f; c[nt][2] = 0.f; c[nt][3] = 0.f;
        }

#pragma unroll 2
        for (int kt = 0; kt < 16; ++kt) {
            int k0 = kt * 8;
            float af[4];
            af[0] = vA ? X[(size_t)rA * Hh + k0 + tig]     : 0.f;
            af[1] = vB ? X[(size_t)rB * Hh + k0 + tig]     : 0.f;
            af[2] = vA ? X[(size_t)rA * Hh + k0 + tig + 4] : 0.f;
            af[3] = vB ? X[(size_t)rB * Hh + k0 + tig + 4] : 0.f;
            uint32_t ahi[4], alo[4];
#pragma unroll
            for (int q = 0; q < 4; ++q) {
                ahi[q] = f2tf32(af[q]);
                alo[q] = f2tf32(af[q] - __uint_as_float(ahi[q]));
            }
#pragma unroll
            for (int nt = 0; nt < 16; ++nt) {
                int n0 = nt * 8;
                uint32_t bh0 = __float_as_uint(Whi[(k0 + tig) * WPAD + n0 + g]);
                uint32_t bh1 = __float_as_uint(Whi[(k0 + tig + 4) * WPAD + n0 + g]);
                uint32_t bl0 = f2tf32(__bfloat162float(Wlo[(k0 + tig) * WPADH + n0 + g]));
                uint32_t bl1 = f2tf32(__bfloat162float(Wlo[(k0 + tig + 4) * WPADH + n0 + g]));
                mma_tf32(c[nt], ahi, bh0, bh1);   // hi*hi
                mma_tf32(c[nt], ahi, bl0, bl1);   // hi*lo
                mma_tf32(c[nt], alo, bh0, bh1);   // lo*hi
            }
        }

        // epilogue: store fp16 H rows + fused fp32 el/er dot products
        float pal = 0.f, par = 0.f, pbl = 0.f, pbr = 0.f;
#pragma unroll
        for (int nt = 0; nt < 16; ++nt) {
            int col = nt * 8 + 2 * tig;     // even -> 4B-aligned half2 store
            if (vA) *(__half2*)&Hout[(size_t)rA * Hh + col] = __floats2half2_rn(c[nt][0], c[nt][1]);
            if (vB) *(__half2*)&Hout[(size_t)rB * Hh + col] = __floats2half2_rn(c[nt][2], c[nt][3]);
            if (compute_elr) {
                float a0 = al[col], a1 = al[col + 1];
                float r0v = ar[col], r1v = ar[col + 1];
                pal += c[nt][0] * a0 + c[nt][1] * a1;
                par += c[nt][0] * r0v + c[nt][1] * r1v;
                pbl += c[nt][2] * a0 + c[nt][3] * a1;
                pbr += c[nt][2] * r0v + c[nt][3] * r1v;
            }
        }
        if (compute_elr) {
#pragma unroll
            for (int o = 1; o < 4; o <<= 1) {
                pal += __shfl_xor_sync(FULL, pal, o);
                par += __shfl_xor_sync(FULL, par, o);
                pbl += __shfl_xor_sync(FULL, pbl, o);
                pbr += __shfl_xor_sync(FULL, pbr, o);
            }
            if (tig == 0) {
                if (vA) { g_el[rA] = pal; g_er[rA] = par; }
                if (vB) { g_el[rB] = pbl; g_er[rB] = pbr; }
            }
        }
    }
}

// ---------------- fused edge softmax + aggregation (single pass, fp16 gather) ----------------
__global__ void agg_kernel(const __half* __restrict__ h, const float* __restrict__ bias,
                           float* __restrict__ hout, int do_relu) {
    int lane = threadIdx.x & 31;
    int v = (blockIdx.x * blockDim.x + threadIdx.x) >> 5;
    if (v >= Nn) return;

    int r0 = g_rowptr[v];
    int r1 = g_rowptr[v + 1];
    float elv = g_el[v];

    float4 acc = make_float4(0.f, 0.f, 0.f, 0.f);
    float s = 0.f;
#pragma unroll 4
    for (int i = r0; i < r1; ++i) {
        int sv = g_ssrc[i];
        float e = elv + g_er[sv];
        e = e > 0.f ? e : 0.2f * e;
        float w = __expf(e);
        s += w;
        uint2 raw = *(const uint2*)(h + (size_t)sv * Hh + lane * 4);
        float2 f0 = __half22float2(*(__half2*)&raw.x);
        float2 f1 = __half22float2(*(__half2*)&raw.y);
        acc.x += w * f0.x;
        acc.y += w * f0.y;
        acc.z += w * f1.x;
        acc.w += w * f1.y;
    }

    float inv = 1.f / (s + 1e-10f);
    float4 bv = *(const float4*)(bias + lane * 4);
    float4 o;
    o.x = acc.x * inv + bv.x;
    o.y = acc.y * inv + bv.y;
    o.z = acc.z * inv + bv.z;
    o.w = acc.w * inv + bv.w;
    if (do_relu) {
        o.x = fmaxf(o.x, 0.f);
        o.y = fmaxf(o.y, 0.f);
        o.z = fmaxf(o.z, 0.f);
        o.w = fmaxf(o.w, 0.f);
    }
    *(float4*)(hout + (size_t)v * Hh + lane * 4) = o;
}

// ---------------- scores = T(fp16) @ server(fp32)^T + bb ----------------
__global__ void scores_kernel(const __half* __restrict__ Tm, const float* __restrict__ S,
                              const float* __restrict__ bb, float* __restrict__ out) {
    const unsigned FULL = 0xffffffffu;
    int lane = threadIdx.x & 31;
    int w = (blockIdx.x * blockDim.x + threadIdx.x) >> 5;
    if (w >= NMc * 8) return;
    int m = w >> 3;
    int sbase = (w & 7) * 32;
    uint2 raw = *(const uint2*)(Tm + (size_t)m * Hh + lane * 4);
    float2 t0 = __half22float2(*(__half2*)&raw.x);
    float2 t1 = __half22float2(*(__half2*)&raw.y);
    float b = bb[0];
    for (int j = 0; j < 32; ++j) {
        int sidx = sbase + j;
        float4 sv = ((const float4*)(S + (size_t)sidx * Hh))[lane];
        float d = t0.x * sv.x + t0.y * sv.y + t1.x * sv.z + t1.y * sv.w;
#pragma unroll
        for (int o = 16; o; o >>= 1) d += __shfl_xor_sync(FULL, d, o);
        if (lane == 0) out[m * NSc + sidx] = d + b;
    }
}

// ---------------- launch ----------------
extern "C" void kernel_launch(void* const* d_in, const int* in_sizes, int n_in,
                              void* d_out, int out_size) {
    (void)in_sizes; (void)n_in; (void)out_size;
    const float* x   = (const float*)d_in[0];
    const int*   ei  = (const int*)d_in[1];
    const float* W1  = (const float*)d_in[2];
    const float* al1 = (const float*)d_in[3];
    const float* ar1 = (const float*)d_in[4];
    const float* b1  = (const float*)d_in[5];
    const float* W2  = (const float*)d_in[6];
    const float* al2 = (const float*)d_in[7];
    const float* ar2 = (const float*)d_in[8];
    const float* b2  = (const float*)d_in[9];
    const float* W3  = (const float*)d_in[10];
    const float* al3 = (const float*)d_in[11];
    const float* ar3 = (const float*)d_in[12];
    const float* b3  = (const float*)d_in[13];
    const float* Wb  = (const float*)d_in[14];
    const float* bb  = (const float*)d_in[15];
    float* out = (float*)d_out;

    const int* src = ei;
    const int* dst = ei + Ee;

    const int SMEM_GEMM = 128 * WPAD * 4 + 128 * WPADH * 2;   // 69632 + 69632 = 139264? no: WPADH*2 bytes = 544B/row*128
    cudaFuncSetAttribute(gemm_tf32_kernel, cudaFuncAttributeMaxDynamicSharedMemorySize, SMEM_GEMM);

    __half *hm, *Tp;
    float *ha, *hb;
    cudaGetSymbolAddress((void**)&hm, g_hm);
    cudaGetSymbolAddress((void**)&ha, g_ha);
    cudaGetSymbolAddress((void**)&hb, g_hb);
    cudaGetSymbolAddress((void**)&Tp, g_T);

    // CSR by dst
    zero_cnt_kernel<<<NB, 256>>>();
    hist_kernel<<<2048, 256>>>(dst);
    scanA_kernel<<<NB, 256>>>();
    scanB_kernel<<<1, 256>>>();
    scanC_kernel<<<NB, 256>>>();
    scatter_kernel<<<2048, 256>>>(src, dst);

    const int GEMM_GRID = 391;
    const int AGG_GRID  = (Nn * 32 + 255) / 256;

    // layer 1
    gemm_tf32_kernel<<<GEMM_GRID, 256, SMEM_GEMM>>>(x, W1, al1, ar1, hm, Nn, 1);
    agg_kernel<<<AGG_GRID, 256>>>(hm, b1, ha, 1);
    // layer 2
    gemm_tf32_kernel<<<GEMM_GRID, 256, SMEM_GEMM>>>(ha, W2, al2, ar2, hm, Nn, 1);
    agg_kernel<<<AGG_GRID, 256>>>(hm, b2, hb, 1);
    // layer 3
    gemm_tf32_kernel<<<GEMM_GRID, 256, SMEM_GEMM>>>(hb, W3, al3, ar3, hm, Nn, 1);
    agg_kernel<<<AGG_GRID, 256>>>(hm, b3, ha, 0);

    // bilinear head: T = model_emb @ Wb (fp16 out), then scores = T @ server^T + bb
    gemm_tf32_kernel<<<4, 256, SMEM_GEMM>>>(ha + (size_t)NUc * Hh, Wb, al1, ar1, Tp, NMc, 0);
    scores_kernel<<<512, 256>>>(Tp, ha + (size_t)(NUc + NMc) * Hh, bb, out);
}